// round 15
// baseline (speedup 1.0000x reference)
#include <cuda_runtime.h>
#include <cuda_bf16.h>
#include <cuda_fp16.h>
#include <math.h>
#include <cstdint>

#define B_SZ     2
#define SEQ      2048
#define D_MODEL  1024
#define D_INNER  2048
#define D_STATE  16
#define DT_RANK  64
#define D_CONV   4
#define NROWS    (B_SZ * SEQ)             // 4096
#define XPROJ_N  (DT_RANK + 2 * D_STATE)  // 96
#define XPROJ_NPAD 128
#define KSPLIT3  8
#define NCH      16                        // scan chunks
#define CHT      (SEQ / NCH)               // 128 steps per chunk
#define SCH      4                         // d-channels per scan block

typedef __half fp16;

// ---------------- scratch (static device globals; no allocation allowed) ---
__device__ __align__(256) fp16  g_xzh[(size_t)NROWS * (2 * D_INNER)];   // fp16 xz
__device__ __align__(256) float g_xdbc[(size_t)NROWS * XPROJ_N];
__device__ __align__(256) float g_part[(size_t)KSPLIT3 * NROWS * XPROJ_NPAD];
// transposed [d][b*SEQ+l] scan inputs, fp16
__device__ __align__(256) fp16 g_dtT[(size_t)D_INNER * NROWS];
__device__ __align__(256) fp16 g_xcT[(size_t)D_INNER * NROWS];
__device__ __align__(256) fp16 g_zT[(size_t)D_INNER * NROWS];
// fp16 activations
__device__ __align__(256) fp16 g_xh[(size_t)NROWS * D_MODEL];
__device__ __align__(256) fp16 g_xconvh[(size_t)NROWS * D_INNER];
__device__ __align__(256) fp16 g_xdh[(size_t)NROWS * DT_RANK];
__device__ __align__(256) fp16 g_yh[(size_t)NROWS * D_INNER];
// fp16 transposed weights [N, K]
__device__ __align__(256) fp16 g_winT[(size_t)(2 * D_INNER) * D_MODEL];
__device__ __align__(256) fp16 g_woutT[(size_t)D_MODEL * D_INNER];
__device__ __align__(256) fp16 g_wxT[(size_t)XPROJ_NPAD * D_INNER];
__device__ __align__(256) fp16 g_wdtT[(size_t)D_INNER * DT_RANK];

// ======================= helpers ===========================================
__device__ __forceinline__ uint32_t smem_u32(const void* p) {
    uint32_t a;
    asm("{ .reg .u64 t; cvta.to.shared.u64 t, %1; cvt.u32.u64 %0, t; }"
        : "=r"(a) : "l"(p));
    return a;
}
__device__ __forceinline__ void cp_async16(uint32_t dst, const void* src) {
    asm volatile("cp.async.cg.shared.global [%0], [%1], 16;"
                 :: "r"(dst), "l"(src));
}
#define CP_COMMIT() asm volatile("cp.async.commit_group;")
#define CP_WAIT0()  asm volatile("cp.async.wait_group 0;")
#define CP_WAIT1()  asm volatile("cp.async.wait_group 1;")

__device__ __forceinline__ void ldsm_x4(uint32_t* r, uint32_t addr) {
    asm volatile("ldmatrix.sync.aligned.m8n8.x4.shared.b16 {%0,%1,%2,%3}, [%4];"
                 : "=r"(r[0]), "=r"(r[1]), "=r"(r[2]), "=r"(r[3]) : "r"(addr));
}

__device__ __forceinline__ void mma16816(float* c, const uint32_t* a,
                                         const uint32_t* b) {
    asm volatile(
        "mma.sync.aligned.m16n8k16.row.col.f32.f16.f16.f32 "
        "{%0,%1,%2,%3}, {%4,%5,%6,%7}, {%8,%9}, {%0,%1,%2,%3};\n"
        : "+f"(c[0]), "+f"(c[1]), "+f"(c[2]), "+f"(c[3])
        : "r"(a[0]), "r"(a[1]), "r"(a[2]), "r"(a[3]),
          "r"(b[0]), "r"(b[1]));
}

// load 4 consecutive fp16 -> 4 floats (8B aligned)
__device__ __forceinline__ void load4h(const fp16* p, float* v) {
    uint2 raw = *reinterpret_cast<const uint2*>(p);
    const __half2* h2 = reinterpret_cast<const __half2*>(&raw);
    float2 f0 = __half22float2(h2[0]);
    float2 f1 = __half22float2(h2[1]);
    v[0] = f0.x; v[1] = f0.y; v[2] = f1.x; v[3] = f1.y;
}

// ===== GEMM: C[M,N] = A * B^T, single-pass fp16, 3-stage cp.async =========
#define ROW_BYTES 80u
#define TILE_B    (128u * ROW_BYTES)    // 10240
#define STAGE_B   (2u * TILE_B)         // 20480 (A|B)
#define NSTAGE    3
#define SMEM_TOT  (NSTAGE * STAGE_B)    // 61440

__global__ void __launch_bounds__(256)
gemm1p(const fp16* __restrict__ A, const fp16* __restrict__ B,
       float* __restrict__ C, fp16* __restrict__ Ch,
       int Nc, int K, int kstart_ch, int kch, int ldc,
       const float* __restrict__ bias, int act, size_t partStride)
{
    extern __shared__ __align__(16) char smem_raw[];
    const uint32_t sb = smem_u32(smem_raw);

    kstart_ch += blockIdx.z * kch;          // split-K slice

    const int tid = threadIdx.x;
    const int wid = tid >> 5, lane = tid & 31;
    const int gr = lane >> 2, q = lane & 3;
    const int row0 = blockIdx.y * 128, col0 = blockIdx.x * 128;
    const int warp_m = (wid & 1) * 64, warp_n = (wid >> 1) * 32;

    float* Cout = C ? (C + (size_t)blockIdx.z * partStride) : nullptr;

    const fp16* tbA = A + (size_t)row0 * K;
    const fp16* tbB = B + (size_t)col0 * K;

    float acc[4][4][4];
#pragma unroll
    for (int i = 0; i < 4; i++)
#pragma unroll
        for (int j = 0; j < 4; j++)
#pragma unroll
            for (int r = 0; r < 4; r++) acc[i][j][r] = 0.f;

    auto load_stage = [&](int c, int s) {
        int koff = (kstart_ch + c) << 5;
#pragma unroll
        for (int i = 0; i < 4; i++) {
            int seg = tid + 256 * i;            // 0..1023
            int buf = seg >> 9;                 // 0 = A, 1 = B
            int w   = seg & 511;
            int row = w >> 2, s4 = w & 3;
            const fp16* base = buf ? tbB : tbA;
            const fp16* g = base + (size_t)row * K + koff + s4 * 8;
            uint32_t dst = sb + (uint32_t)s * STAGE_B + (uint32_t)buf * TILE_B
                         + (uint32_t)row * ROW_BYTES + (uint32_t)s4 * 16u;
            cp_async16(dst, g);
        }
    };

    const uint32_t a_row  = (uint32_t)(lane & 15);
    const uint32_t a_koff = (uint32_t)(lane >> 4) * 16u;
    const uint32_t b_row  = (uint32_t)(((lane >> 4) << 3) + (lane & 7));
    const uint32_t b_koff = (uint32_t)((lane >> 3) & 1) * 16u;

    load_stage(0, 0);
    CP_COMMIT();
    if (kch > 1) { load_stage(1, 1); CP_COMMIT(); }

    int snext = 2;
    for (int c = 0; c < kch; c++) {
        if (c + 1 < kch) CP_WAIT1();
        else             CP_WAIT0();
        __syncthreads();
        if (c + 2 < kch) {
            load_stage(c + 2, snext);
            CP_COMMIT();
        }

        const uint32_t st = sb + (uint32_t)(c - (c / NSTAGE) * NSTAGE) * STAGE_B;
        const uint32_t sA = st;
        const uint32_t sB = st + TILE_B;
        snext = snext + 1 == NSTAGE ? 0 : snext + 1;

#pragma unroll
        for (int kc = 0; kc < 2; kc++) {
            uint32_t aH[4][4], bH[8];
#pragma unroll
            for (int mt = 0; mt < 4; mt++) {
                uint32_t roff = ((uint32_t)(warp_m + mt * 16) + a_row) * ROW_BYTES
                              + kc * 32u + a_koff;
                ldsm_x4(aH[mt], sA + roff);
            }
            {
                uint32_t r0 = ((uint32_t)warp_n + b_row) * ROW_BYTES
                            + kc * 32u + b_koff;
                uint32_t r1 = r0 + 16u * ROW_BYTES;
                ldsm_x4(bH + 0, sB + r0);
                ldsm_x4(bH + 4, sB + r1);
            }
#pragma unroll
            for (int mt = 0; mt < 4; mt++)
#pragma unroll
                for (int nt = 0; nt < 4; nt++)
                    mma16816(acc[mt][nt], aH[mt], bH + nt * 2);
        }
    }

    // ---------------- epilogue ----------------
#pragma unroll
    for (int mt = 0; mt < 4; mt++) {
#pragma unroll
        for (int nt = 0; nt < 4; nt++) {
            int rg = row0 + warp_m + mt * 16 + gr;
            int cg = col0 + warp_n + nt * 8 + 2 * q;
            float* cc = acc[mt][nt];
#pragma unroll
            for (int half = 0; half < 2; half++) {
                int r = rg + half * 8;
                float v0 = cc[half * 2 + 0];
                float v1 = cc[half * 2 + 1];
                if (bias) {
                    if (act == 2) { float bb = bias[r]; v0 += bb; v1 += bb; }
                    else          { v0 += bias[cg]; v1 += bias[cg + 1]; }
                }
                if (act) {
                    v0 = (v0 > 20.f) ? v0 : log1pf(expf(v0));
                    v1 = (v1 > 20.f) ? v1 : log1pf(expf(v1));
                }
                if (cg + 1 < Nc) {
                    if (Ch) {
                        *reinterpret_cast<__half2*>(&Ch[(size_t)r * ldc + cg]) =
                            __floats2half2_rn(v0, v1);
                    } else {
                        *reinterpret_cast<float2*>(&Cout[(size_t)r * ldc + cg]) =
                            make_float2(v0, v1);
                    }
                } else if (cg < Nc) {
                    if (Ch) Ch[(size_t)r * ldc + cg] = __float2half_rn(v0);
                    else    Cout[(size_t)r * ldc + cg] = v0;
                }
            }
        }
    }
}

// -------- split-K reduce for xproj GEMM: sum partials, write xdbc + xdh ----
__global__ void reduce3_kernel(const float* __restrict__ part,
                               float* __restrict__ xdbc,
                               fp16* __restrict__ xdh)
{
    int i = blockIdx.x * 256 + threadIdx.x;
    if (i >= NROWS * XPROJ_N) return;
    int r = i / XPROJ_N, c = i - r * XPROJ_N;
    const size_t ps = (size_t)NROWS * XPROJ_NPAD;
    float v = 0.f;
#pragma unroll
    for (int p = 0; p < KSPLIT3; p++)
        v += part[p * ps + (size_t)r * XPROJ_NPAD + c];
    xdbc[(size_t)r * XPROJ_N + c] = v;
    if (c < DT_RANK)
        xdh[(size_t)r * DT_RANK + c] = __float2half_rn(v);
}

// ====== unified prep: fp32->fp16 input convert + 4 weight transposes =======
__device__ __forceinline__ void wsplit_body(const float* __restrict__ W,
                                            fp16* __restrict__ Th,
                                            int K, int N, int Npad,
                                            int bx, int by, int tx, int ty)
{
    __shared__ float tile[32][33];
    int kb = by * 32, nb = bx * 32;
#pragma unroll
    for (int i = ty; i < 32; i += 8) {
        int k = kb + i, n = nb + tx;
        tile[i][tx] = (k < K && n < N) ? W[(size_t)k * N + n] : 0.f;
    }
    __syncthreads();
#pragma unroll
    for (int i = ty; i < 32; i += 8) {
        int n = nb + i, k = kb + tx;
        if (n < Npad && k < K)
            Th[(size_t)n * K + k] = __float2half_rn(tile[tx][i]);
    }
}

#define PREP_FCONV 2048   // 4M elems / 8 per thread / 256 threads
#define PREP_WIN   4096   // (4096/32) x (1024/32)
#define PREP_WX    256    // (128/32) x (2048/32)
#define PREP_WDT   128    // (2048/32) x (64/32)
#define PREP_WOUT  2048   // (1024/32) x (2048/32)
#define PREP_TOTAL (PREP_FCONV + PREP_WIN + PREP_WX + PREP_WDT + PREP_WOUT)

__global__ void __launch_bounds__(256)
prep_kernel(const float* __restrict__ x,    fp16* __restrict__ xh,
            const float* __restrict__ w_in, fp16* __restrict__ winT,
            const float* __restrict__ w_x,  fp16* __restrict__ wxT,
            const float* __restrict__ w_dt, fp16* __restrict__ wdtT,
            const float* __restrict__ w_o,  fp16* __restrict__ woutT)
{
    int blk = blockIdx.x;
    int tid = threadIdx.x;
    int tx = tid & 31, ty = tid >> 5;

    if (blk < PREP_FCONV) {
        int i = (blk * 256 + tid) * 8;
        float4 a = *reinterpret_cast<const float4*>(x + i);
        float4 b = *reinterpret_cast<const float4*>(x + i + 4);
        __half2 h0 = __floats2half2_rn(a.x, a.y);
        __half2 h1 = __floats2half2_rn(a.z, a.w);
        __half2 h2 = __floats2half2_rn(b.x, b.y);
        __half2 h3 = __floats2half2_rn(b.z, b.w);
        uint4 o;
        o.x = *reinterpret_cast<uint32_t*>(&h0);
        o.y = *reinterpret_cast<uint32_t*>(&h1);
        o.z = *reinterpret_cast<uint32_t*>(&h2);
        o.w = *reinterpret_cast<uint32_t*>(&h3);
        *reinterpret_cast<uint4*>(xh + i) = o;
        return;
    }
    blk -= PREP_FCONV;
    if (blk < PREP_WIN) {
        wsplit_body(w_in, winT, D_MODEL, 2 * D_INNER, 2 * D_INNER,
                    blk % 128, blk / 128, tx, ty);
        return;
    }
    blk -= PREP_WIN;
    if (blk < PREP_WX) {
        wsplit_body(w_x, wxT, D_INNER, XPROJ_N, XPROJ_NPAD,
                    blk % 4, blk / 4, tx, ty);
        return;
    }
    blk -= PREP_WX;
    if (blk < PREP_WDT) {
        wsplit_body(w_dt, wdtT, DT_RANK, D_INNER, D_INNER,
                    blk % 64, blk / 64, tx, ty);
        return;
    }
    blk -= PREP_WDT;
    wsplit_body(w_o, woutT, D_INNER, D_MODEL, D_MODEL,
                blk % 32, blk / 32, tx, ty);
}

// ====== fused causal conv + SiLU + transposes (fp16 xz input) ==============
__global__ void convT_kernel(const fp16* __restrict__ xz,
                             const float* __restrict__ w_conv,
                             const float* __restrict__ b_conv,
                             fp16* __restrict__ xcT, fp16* __restrict__ zT,
                             fp16* __restrict__ xch)
{
    __shared__ float tin[35][33];
    __shared__ float tout[32][33];
    __shared__ float tz[32][33];
    const int b  = blockIdx.z;
    const int l0 = blockIdx.x * 32, d0 = blockIdx.y * 32;
    const int tx = threadIdx.x, ty = threadIdx.y;     // 32 x 8

    for (int j = ty; j < 35; j += 8) {
        int l = l0 - 3 + j;
        tin[j][tx] = (l >= 0)
            ? __half2float(xz[(size_t)(b * SEQ + l) * (2 * D_INNER) + d0 + tx])
            : 0.f;
    }
#pragma unroll
    for (int i = ty; i < 32; i += 8)
        tz[i][tx] = __half2float(
            xz[(size_t)(b * SEQ + l0 + i) * (2 * D_INNER) + D_INNER + d0 + tx]);
    __syncthreads();

    const float w0 = w_conv[(d0 + tx) * D_CONV + 0];
    const float w1 = w_conv[(d0 + tx) * D_CONV + 1];
    const float w2 = w_conv[(d0 + tx) * D_CONV + 2];
    const float w3 = w_conv[(d0 + tx) * D_CONV + 3];
    const float bc = b_conv[d0 + tx];
#pragma unroll
    for (int i = ty; i < 32; i += 8) {
        float acc = bc + tin[i][tx] * w0 + tin[i + 1][tx] * w1
                       + tin[i + 2][tx] * w2 + tin[i + 3][tx] * w3;
        float s = 1.f / (1.f + __expf(-acc));
        float v = acc * s;
        tout[i][tx] = v;
        xch[(size_t)(b * SEQ + l0 + i) * D_INNER + d0 + tx] = __float2half_rn(v);
    }
    __syncthreads();
#pragma unroll
    for (int i = ty; i < 32; i += 8) {
        size_t o = (size_t)(d0 + i) * NROWS + b * SEQ + l0 + tx;
        xcT[o] = __float2half_rn(tout[tx][i]);
        zT[o]  = __float2half_rn(tz[tx][i]);
    }
}

// ========== fused chunked selective scan, SCH=4 channels per block =========
__global__ void __launch_bounds__(256)
scan_fused_kernel(const fp16* __restrict__ dtT, const fp16* __restrict__ xcT,
                  const fp16* __restrict__ zT,  const float* __restrict__ xdbc,
                  const float* __restrict__ A_log, const float* __restrict__ Dv,
                  fp16* __restrict__ yh)
{
    __shared__ float sP[NCH][SCH][D_STATE];
    __shared__ float sS[NCH][SCH][D_STATE];

    const int blk = blockIdx.x;
    const int dgrp = blk & (D_INNER / SCH - 1);
    const int b    = blk >> 9;
    const int d0   = dgrp * SCH;
    const int t = threadIdx.x;
    const int n = t & 15, c = t >> 4;

    float An[SCH], Dd[SCH];
#pragma unroll
    for (int ch = 0; ch < SCH; ch++) {
        An[ch] = -expf(A_log[(d0 + ch) * D_STATE + n]);
        Dd[ch] = Dv[d0 + ch];
    }

    const size_t base = (size_t)d0 * NROWS + b * SEQ + c * CHT;
    const fp16* dtp = dtT + base;
    const fp16* xcp = xcT + base;
    const fp16* zp  = zT  + base;
    const float* bc0 = xdbc + ((size_t)(b * SEQ + c * CHT)) * XPROJ_N;

    // ---- Phase A ----
    {
        const float* bc = bc0;
        float P[SCH], S[SCH];
#pragma unroll
        for (int ch = 0; ch < SCH; ch++) { P[ch] = 1.f; S[ch] = 0.f; }
        for (int l0 = 0; l0 < CHT; l0 += 4) {
            float dt4[SCH][4], xc4[SCH][4];
#pragma unroll
            for (int ch = 0; ch < SCH; ch++) {
                load4h(dtp + (size_t)ch * NROWS + l0, dt4[ch]);
                load4h(xcp + (size_t)ch * NROWS + l0, xc4[ch]);
            }
#pragma unroll
            for (int j = 0; j < 4; j++) {
                float Bn = bc[DT_RANK + n];
#pragma unroll
                for (int ch = 0; ch < SCH; ch++) {
                    float a = __expf(dt4[ch][j] * An[ch]);
                    S[ch] = fmaf(a, S[ch], dt4[ch][j] * xc4[ch][j] * Bn);
                    P[ch] *= a;
                }
                bc += XPROJ_N;
            }
        }
#pragma unroll
        for (int ch = 0; ch < SCH; ch++) { sP[c][ch][n] = P[ch]; sS[c][ch][n] = S[ch]; }
    }
    __syncthreads();

    // ---- Phase B ----
    float h[SCH];
#pragma unroll
    for (int ch = 0; ch < SCH; ch++) h[ch] = 0.f;
    for (int cc = 0; cc < c; cc++)
#pragma unroll
        for (int ch = 0; ch < SCH; ch++)
            h[ch] = fmaf(sP[cc][ch][n], h[ch], sS[cc][ch][n]);

    // ---- Phase C ----
    const float* bc = bc0;
    size_t yrow = (size_t)(b * SEQ + c * CHT) * D_INNER + d0;

    for (int l0 = 0; l0 < CHT; l0 += 4) {
        float dt4[SCH][4], xc4[SCH][4];
#pragma unroll
        for (int ch = 0; ch < SCH; ch++) {
            load4h(dtp + (size_t)ch * NROWS + l0, dt4[ch]);
            load4h(xcp + (size_t)ch * NROWS + l0, xc4[ch]);
        }
#pragma unroll
        for (int j = 0; j < 4; j++) {
            float Bn = bc[DT_RANK + n];
            float Cn = bc[DT_RANK + D_STATE + n];
            float part[SCH];
#pragma unroll
            for (int ch = 0; ch < SCH; ch++) {
                float a = __expf(dt4[ch][j] * An[ch]);
                h[ch] = fmaf(a, h[ch], dt4[ch][j] * xc4[ch][j] * Bn);
                part[ch] = Cn * h[ch];
            }
#pragma unroll
            for (int ch = 0; ch < SCH; ch++) {
                part[ch] += __shfl_xor_sync(0xffffffffu, part[ch], 1);
                part[ch] += __shfl_xor_sync(0xffffffffu, part[ch], 2);
                part[ch] += __shfl_xor_sync(0xffffffffu, part[ch], 4);
                part[ch] += __shfl_xor_sync(0xffffffffu, part[ch], 8);
            }
            if (n == 0) {
                float z0 = __half2float(zp[l0 + j]);
                float z1 = __half2float(zp[(size_t)1 * NROWS + l0 + j]);
                float z2 = __half2float(zp[(size_t)2 * NROWS + l0 + j]);
                float z3 = __half2float(zp[(size_t)3 * NROWS + l0 + j]);
                float g0 = z0 / (1.f + __expf(-z0));
                float g1 = z1 / (1.f + __expf(-z1));
                float g2 = z2 / (1.f + __expf(-z2));
                float g3 = z3 / (1.f + __expf(-z3));
                __half2 o01 = __floats2half2_rn(
                    (part[0] + xc4[0][j] * Dd[0]) * g0,
                    (part[1] + xc4[1][j] * Dd[1]) * g1);
                __half2 o23 = __floats2half2_rn(
                    (part[2] + xc4[2][j] * Dd[2]) * g2,
                    (part[3] + xc4[3][j] * Dd[3]) * g3);
                uint2 ov;
                ov.x = *reinterpret_cast<uint32_t*>(&o01);
                ov.y = *reinterpret_cast<uint32_t*>(&o23);
                *reinterpret_cast<uint2*>(&yh[yrow]) = ov;
            }
            bc += XPROJ_N;
            yrow += D_INNER;
        }
    }
}

// ---------------- launcher -------------------------------------------------
extern "C" void kernel_launch(void* const* d_in, const int* in_sizes, int n_in,
                              void* d_out, int out_size)
{
    const float* x       = (const float*)d_in[0];
    const float* w_in    = (const float*)d_in[1];
    const float* w_conv  = (const float*)d_in[2];
    const float* b_conv  = (const float*)d_in[3];
    const float* w_xproj = (const float*)d_in[4];
    const float* w_dt    = (const float*)d_in[5];
    const float* b_dt    = (const float*)d_in[6];
    const float* A_log   = (const float*)d_in[7];
    const float* Dv      = (const float*)d_in[8];
    const float* w_out   = (const float*)d_in[9];
    float* out = (float*)d_out;

    float *xdbc, *part;
    fp16 *xzh, *dtT, *xcT, *zT;
    fp16 *xh, *xch, *xdh, *yh;
    fp16 *winT, *woutT, *wxT, *wdtT;
    cudaGetSymbolAddress((void**)&xzh,   g_xzh);
    cudaGetSymbolAddress((void**)&xdbc,  g_xdbc);
    cudaGetSymbolAddress((void**)&part,  g_part);
    cudaGetSymbolAddress((void**)&dtT,   g_dtT);
    cudaGetSymbolAddress((void**)&xcT,   g_xcT);
    cudaGetSymbolAddress((void**)&zT,    g_zT);
    cudaGetSymbolAddress((void**)&xh,    g_xh);
    cudaGetSymbolAddress((void**)&xch,   g_xconvh);
    cudaGetSymbolAddress((void**)&xdh,   g_xdh);
    cudaGetSymbolAddress((void**)&yh,    g_yh);
    cudaGetSymbolAddress((void**)&winT,  g_winT);
    cudaGetSymbolAddress((void**)&woutT, g_woutT);
    cudaGetSymbolAddress((void**)&wxT,   g_wxT);
    cudaGetSymbolAddress((void**)&wdtT,  g_wdtT);

    cudaFuncSetAttribute(gemm1p, cudaFuncAttributeMaxDynamicSharedMemorySize,
                         SMEM_TOT);

    dim3 tb(32, 8);
    // 0: unified prep (input convert + all weight transposes)
    prep_kernel<<<PREP_TOTAL, 256>>>(x, xh, w_in, winT, w_xproj, wxT,
                                     w_dt, wdtT, w_out, woutT);
    // 1: xz = x @ w_in   (fp16 output)
    gemm1p<<<dim3(32, 32, 1), 256, SMEM_TOT>>>(xh, winT, nullptr, xzh,
                                               2 * D_INNER, D_MODEL, 0,
                                               D_MODEL / 32, 2 * D_INNER,
                                               nullptr, 0, 0);
    // 2: fused conv + silu + transposes (fp16 xz)
    convT_kernel<<<dim3(SEQ / 32, D_INNER / 32, B_SZ), tb>>>(
        xzh, w_conv, b_conv, xcT, zT, xch);
    // 3: xproj split-K GEMM                        <-- profiled this round
    gemm1p<<<dim3(1, 32, KSPLIT3), 256, SMEM_TOT>>>(
        xch, wxT, part, nullptr,
        XPROJ_NPAD, D_INNER, 0, (D_INNER / 32) / KSPLIT3, XPROJ_NPAD,
        nullptr, 0, (size_t)NROWS * XPROJ_NPAD);
    // 4: reduce partials (+ dt-rank fp16)
    reduce3_kernel<<<(NROWS * XPROJ_N + 255) / 256, 256>>>(part, xdbc, xdh);
    // 5: dtT = softplus(wdtT @ xdh^T + b_dt[d])  (fp16, transposed layout)
    gemm1p<<<dim3(NROWS / 128, D_INNER / 128, 1), 256, SMEM_TOT>>>(
        wdtT, xdh, nullptr, dtT,
        NROWS, DT_RANK, 0, DT_RANK / 32, NROWS,
        b_dt, 2, 0);
    // 6: fused chunked scan
    scan_fused_kernel<<<B_SZ * D_INNER / SCH, 256>>>(
        dtT, xcT, zT, xdbc, A_log, Dv, yh);
    // 7: out = y @ w_out
    gemm1p<<<dim3(8, 32, 1), 256, SMEM_TOT>>>(yh, woutT, out, nullptr,
                                              D_MODEL, D_INNER, 0,
                                              D_INNER / 32, D_MODEL,
                                              nullptr, 0, 0);
}

// round 16
// speedup vs baseline: 1.4994x; 1.4994x over previous
#include <cuda_runtime.h>
#include <cuda_bf16.h>
#include <cuda_fp16.h>
#include <math.h>
#include <cstdint>

#define B_SZ     2
#define SEQ      2048
#define D_MODEL  1024
#define D_INNER  2048
#define D_STATE  16
#define DT_RANK  64
#define D_CONV   4
#define NROWS    (B_SZ * SEQ)             // 4096
#define XPROJ_N  (DT_RANK + 2 * D_STATE)  // 96
#define XPROJ_NPAD 128
#define KSPLIT3  8
#define NCH      16                        // scan chunks
#define CHT      (SEQ / NCH)               // 128 steps per chunk
#define SCH      4                         // d-channels per scan block

typedef __half fp16;

// ---------------- scratch (static device globals; no allocation allowed) ---
__device__ __align__(256) float g_xz[(size_t)NROWS * (2 * D_INNER)];
__device__ __align__(256) float g_xdbc[(size_t)NROWS * XPROJ_N];
__device__ __align__(256) float g_part[(size_t)KSPLIT3 * NROWS * XPROJ_NPAD];
// transposed [d][b*SEQ+l] scan inputs, fp16
__device__ __align__(256) fp16 g_dtT[(size_t)D_INNER * NROWS];
__device__ __align__(256) fp16 g_xcT[(size_t)D_INNER * NROWS];
__device__ __align__(256) fp16 g_zT[(size_t)D_INNER * NROWS];
// fp16 activations
__device__ __align__(256) fp16 g_xh[(size_t)NROWS * D_MODEL];
__device__ __align__(256) fp16 g_xconvh[(size_t)NROWS * D_INNER];
__device__ __align__(256) fp16 g_xdh[(size_t)NROWS * DT_RANK];
__device__ __align__(256) fp16 g_yh[(size_t)NROWS * D_INNER];
// fp16 transposed weights [N, K]
__device__ __align__(256) fp16 g_winT[(size_t)(2 * D_INNER) * D_MODEL];
__device__ __align__(256) fp16 g_woutT[(size_t)D_MODEL * D_INNER];
__device__ __align__(256) fp16 g_wxT[(size_t)XPROJ_NPAD * D_INNER];
__device__ __align__(256) fp16 g_wdtT[(size_t)D_INNER * DT_RANK];

// ======================= helpers ===========================================
__device__ __forceinline__ uint32_t smem_u32(const void* p) {
    uint32_t a;
    asm("{ .reg .u64 t; cvta.to.shared.u64 t, %1; cvt.u32.u64 %0, t; }"
        : "=r"(a) : "l"(p));
    return a;
}
__device__ __forceinline__ void cp_async16(uint32_t dst, const void* src) {
    asm volatile("cp.async.cg.shared.global [%0], [%1], 16;"
                 :: "r"(dst), "l"(src));
}
#define CP_COMMIT() asm volatile("cp.async.commit_group;")
#define CP_WAIT0()  asm volatile("cp.async.wait_group 0;")
#define CP_WAIT1()  asm volatile("cp.async.wait_group 1;")

__device__ __forceinline__ void ldsm_x4(uint32_t* r, uint32_t addr) {
    asm volatile("ldmatrix.sync.aligned.m8n8.x4.shared.b16 {%0,%1,%2,%3}, [%4];"
                 : "=r"(r[0]), "=r"(r[1]), "=r"(r[2]), "=r"(r[3]) : "r"(addr));
}

__device__ __forceinline__ void mma16816(float* c, const uint32_t* a,
                                         const uint32_t* b) {
    asm volatile(
        "mma.sync.aligned.m16n8k16.row.col.f32.f16.f16.f32 "
        "{%0,%1,%2,%3}, {%4,%5,%6,%7}, {%8,%9}, {%0,%1,%2,%3};\n"
        : "+f"(c[0]), "+f"(c[1]), "+f"(c[2]), "+f"(c[3])
        : "r"(a[0]), "r"(a[1]), "r"(a[2]), "r"(a[3]),
          "r"(b[0]), "r"(b[1]));
}

// load 4 consecutive fp16 -> 4 floats (8B aligned)
__device__ __forceinline__ void load4h(const fp16* p, float* v) {
    uint2 raw = *reinterpret_cast<const uint2*>(p);
    const __half2* h2 = reinterpret_cast<const __half2*>(&raw);
    float2 f0 = __half22float2(h2[0]);
    float2 f1 = __half22float2(h2[1]);
    v[0] = f0.x; v[1] = f0.y; v[2] = f1.x; v[3] = f1.y;
}

// ===== GEMM: C[M,N] = A * B^T, single-pass fp16, 3-stage cp.async =========
#define ROW_BYTES 80u
#define TILE_B    (128u * ROW_BYTES)    // 10240
#define STAGE_B   (2u * TILE_B)         // 20480 (A|B)
#define NSTAGE    3
#define SMEM_TOT  (NSTAGE * STAGE_B)    // 61440

__global__ void __launch_bounds__(256)
gemm1p(const fp16* __restrict__ A, const fp16* __restrict__ B,
       float* __restrict__ C, fp16* __restrict__ Ch,
       int Nc, int K, int kstart_ch, int kch, int ldc,
       const float* __restrict__ bias, int act, size_t partStride)
{
    extern __shared__ __align__(16) char smem_raw[];
    const uint32_t sb = smem_u32(smem_raw);

    kstart_ch += blockIdx.z * kch;          // split-K slice

    const int tid = threadIdx.x;
    const int wid = tid >> 5, lane = tid & 31;
    const int gr = lane >> 2, q = lane & 3;
    const int row0 = blockIdx.y * 128, col0 = blockIdx.x * 128;
    const int warp_m = (wid & 1) * 64, warp_n = (wid >> 1) * 32;

    float* Cout = C ? (C + (size_t)blockIdx.z * partStride) : nullptr;

    const fp16* tbA = A + (size_t)row0 * K;
    const fp16* tbB = B + (size_t)col0 * K;

    float acc[4][4][4];
#pragma unroll
    for (int i = 0; i < 4; i++)
#pragma unroll
        for (int j = 0; j < 4; j++)
#pragma unroll
            for (int r = 0; r < 4; r++) acc[i][j][r] = 0.f;

    auto load_stage = [&](int c, int s) {
        int koff = (kstart_ch + c) << 5;
#pragma unroll
        for (int i = 0; i < 4; i++) {
            int seg = tid + 256 * i;            // 0..1023
            int buf = seg >> 9;                 // 0 = A, 1 = B
            int w   = seg & 511;
            int row = w >> 2, s4 = w & 3;
            const fp16* base = buf ? tbB : tbA;
            const fp16* g = base + (size_t)row * K + koff + s4 * 8;
            uint32_t dst = sb + (uint32_t)s * STAGE_B + (uint32_t)buf * TILE_B
                         + (uint32_t)row * ROW_BYTES + (uint32_t)s4 * 16u;
            cp_async16(dst, g);
        }
    };

    const uint32_t a_row  = (uint32_t)(lane & 15);
    const uint32_t a_koff = (uint32_t)(lane >> 4) * 16u;
    const uint32_t b_row  = (uint32_t)(((lane >> 4) << 3) + (lane & 7));
    const uint32_t b_koff = (uint32_t)((lane >> 3) & 1) * 16u;

    load_stage(0, 0);
    CP_COMMIT();
    if (kch > 1) { load_stage(1, 1); CP_COMMIT(); }

    int snext = 2;
    for (int c = 0; c < kch; c++) {
        if (c + 1 < kch) CP_WAIT1();
        else             CP_WAIT0();
        __syncthreads();
        if (c + 2 < kch) {
            load_stage(c + 2, snext);
            CP_COMMIT();
        }

        const uint32_t st = sb + (uint32_t)(c - (c / NSTAGE) * NSTAGE) * STAGE_B;
        const uint32_t sA = st;
        const uint32_t sB = st + TILE_B;
        snext = snext + 1 == NSTAGE ? 0 : snext + 1;

#pragma unroll
        for (int kc = 0; kc < 2; kc++) {
            uint32_t aH[4][4], bH[8];
#pragma unroll
            for (int mt = 0; mt < 4; mt++) {
                uint32_t roff = ((uint32_t)(warp_m + mt * 16) + a_row) * ROW_BYTES
                              + kc * 32u + a_koff;
                ldsm_x4(aH[mt], sA + roff);
            }
            {
                uint32_t r0 = ((uint32_t)warp_n + b_row) * ROW_BYTES
                            + kc * 32u + b_koff;
                uint32_t r1 = r0 + 16u * ROW_BYTES;
                ldsm_x4(bH + 0, sB + r0);
                ldsm_x4(bH + 4, sB + r1);
            }
#pragma unroll
            for (int mt = 0; mt < 4; mt++)
#pragma unroll
                for (int nt = 0; nt < 4; nt++)
                    mma16816(acc[mt][nt], aH[mt], bH + nt * 2);
        }
    }

    // ---------------- epilogue ----------------
#pragma unroll
    for (int mt = 0; mt < 4; mt++) {
#pragma unroll
        for (int nt = 0; nt < 4; nt++) {
            int rg = row0 + warp_m + mt * 16 + gr;
            int cg = col0 + warp_n + nt * 8 + 2 * q;
            float* cc = acc[mt][nt];
#pragma unroll
            for (int half = 0; half < 2; half++) {
                int r = rg + half * 8;
                float v0 = cc[half * 2 + 0];
                float v1 = cc[half * 2 + 1];
                if (bias) {
                    if (act == 2) { float bb = bias[r]; v0 += bb; v1 += bb; }
                    else          { v0 += bias[cg]; v1 += bias[cg + 1]; }
                }
                if (act) {
                    v0 = (v0 > 20.f) ? v0 : log1pf(expf(v0));
                    v1 = (v1 > 20.f) ? v1 : log1pf(expf(v1));
                }
                if (cg + 1 < Nc) {
                    if (Ch) {
                        *reinterpret_cast<__half2*>(&Ch[(size_t)r * ldc + cg]) =
                            __floats2half2_rn(v0, v1);
                    } else {
                        *reinterpret_cast<float2*>(&Cout[(size_t)r * ldc + cg]) =
                            make_float2(v0, v1);
                    }
                } else if (cg < Nc) {
                    if (Ch) Ch[(size_t)r * ldc + cg] = __float2half_rn(v0);
                    else    Cout[(size_t)r * ldc + cg] = v0;
                }
            }
        }
    }
}

// -------- split-K reduce for xproj GEMM: sum partials, write xdbc + xdh ----
__global__ void reduce3_kernel(const float* __restrict__ part,
                               float* __restrict__ xdbc,
                               fp16* __restrict__ xdh)
{
    int i = blockIdx.x * 256 + threadIdx.x;
    if (i >= NROWS * XPROJ_N) return;
    int r = i / XPROJ_N, c = i - r * XPROJ_N;
    const size_t ps = (size_t)NROWS * XPROJ_NPAD;
    float v = 0.f;
#pragma unroll
    for (int p = 0; p < KSPLIT3; p++)
        v += part[p * ps + (size_t)r * XPROJ_NPAD + c];
    xdbc[(size_t)r * XPROJ_N + c] = v;
    if (c < DT_RANK)
        xdh[(size_t)r * DT_RANK + c] = __float2half_rn(v);
}

// ====== unified prep: fp32->fp16 input convert + 4 weight transposes =======
__device__ __forceinline__ void wsplit_body(const float* __restrict__ W,
                                            fp16* __restrict__ Th,
                                            int K, int N, int Npad,
                                            int bx, int by, int tx, int ty)
{
    __shared__ float tile[32][33];
#pragma unroll
    for (int i = ty; i < 32; i += 8) {
        int k = by * 32 + i, n = bx * 32 + tx;
        tile[i][tx] = (k < K && n < N) ? W[(size_t)k * N + n] : 0.f;
    }
    __syncthreads();
#pragma unroll
    for (int i = ty; i < 32; i += 8) {
        int n = bx * 32 + i, k = by * 32 + tx;
        if (n < Npad && k < K)
            Th[(size_t)n * K + k] = __float2half_rn(tile[tx][i]);
    }
}

#define PREP_FCONV 2048   // 4M elems / 8 per thread / 256 threads
#define PREP_WIN   4096
#define PREP_WX    256
#define PREP_WDT   128
#define PREP_WOUT  2048
#define PREP_TOTAL (PREP_FCONV + PREP_WIN + PREP_WX + PREP_WDT + PREP_WOUT)

__global__ void __launch_bounds__(256)
prep_kernel(const float* __restrict__ x,    fp16* __restrict__ xh,
            const float* __restrict__ w_in, fp16* __restrict__ winT,
            const float* __restrict__ w_x,  fp16* __restrict__ wxT,
            const float* __restrict__ w_dt, fp16* __restrict__ wdtT,
            const float* __restrict__ w_o,  fp16* __restrict__ woutT)
{
    int blk = blockIdx.x;
    int tid = threadIdx.x;
    int tx = tid & 31, ty = tid >> 5;

    if (blk < PREP_FCONV) {
        int i = (blk * 256 + tid) * 8;
        float4 a = *reinterpret_cast<const float4*>(x + i);
        float4 b = *reinterpret_cast<const float4*>(x + i + 4);
        __half2 h0 = __floats2half2_rn(a.x, a.y);
        __half2 h1 = __floats2half2_rn(a.z, a.w);
        __half2 h2 = __floats2half2_rn(b.x, b.y);
        __half2 h3 = __floats2half2_rn(b.z, b.w);
        uint4 o;
        o.x = *reinterpret_cast<uint32_t*>(&h0);
        o.y = *reinterpret_cast<uint32_t*>(&h1);
        o.z = *reinterpret_cast<uint32_t*>(&h2);
        o.w = *reinterpret_cast<uint32_t*>(&h3);
        *reinterpret_cast<uint4*>(xh + i) = o;
        return;
    }
    blk -= PREP_FCONV;
    if (blk < PREP_WIN) {
        wsplit_body(w_in, winT, D_MODEL, 2 * D_INNER, 2 * D_INNER,
                    blk % 128, blk / 128, tx, ty);
        return;
    }
    blk -= PREP_WIN;
    if (blk < PREP_WX) {
        wsplit_body(w_x, wxT, D_INNER, XPROJ_N, XPROJ_NPAD,
                    blk % 4, blk / 4, tx, ty);
        return;
    }
    blk -= PREP_WX;
    if (blk < PREP_WDT) {
        wsplit_body(w_dt, wdtT, DT_RANK, D_INNER, D_INNER,
                    blk % 64, blk / 64, tx, ty);
        return;
    }
    blk -= PREP_WDT;
    wsplit_body(w_o, woutT, D_INNER, D_MODEL, D_MODEL,
                blk % 32, blk / 32, tx, ty);
}

// ====== fused causal conv + SiLU + transposes (fp32 xz, one pass) ==========
__global__ void convT_kernel(const float* __restrict__ xz,
                             const float* __restrict__ w_conv,
                             const float* __restrict__ b_conv,
                             fp16* __restrict__ xcT, fp16* __restrict__ zT,
                             fp16* __restrict__ xch)
{
    __shared__ float tin[35][33];
    __shared__ float tout[32][33];
    __shared__ float tz[32][33];
    const int b  = blockIdx.z;
    const int l0 = blockIdx.x * 32, d0 = blockIdx.y * 32;
    const int tx = threadIdx.x, ty = threadIdx.y;     // 32 x 8

    for (int j = ty; j < 35; j += 8) {
        int l = l0 - 3 + j;
        tin[j][tx] = (l >= 0) ? xz[(size_t)(b * SEQ + l) * (2 * D_INNER) + d0 + tx]
                              : 0.f;
    }
#pragma unroll
    for (int i = ty; i < 32; i += 8)
        tz[i][tx] = xz[(size_t)(b * SEQ + l0 + i) * (2 * D_INNER) + D_INNER + d0 + tx];
    __syncthreads();

    const float w0 = w_conv[(d0 + tx) * D_CONV + 0];
    const float w1 = w_conv[(d0 + tx) * D_CONV + 1];
    const float w2 = w_conv[(d0 + tx) * D_CONV + 2];
    const float w3 = w_conv[(d0 + tx) * D_CONV + 3];
    const float bc = b_conv[d0 + tx];
#pragma unroll
    for (int i = ty; i < 32; i += 8) {
        float acc = bc + tin[i][tx] * w0 + tin[i + 1][tx] * w1
                       + tin[i + 2][tx] * w2 + tin[i + 3][tx] * w3;
        float s = 1.f / (1.f + __expf(-acc));
        float v = acc * s;
        tout[i][tx] = v;
        xch[(size_t)(b * SEQ + l0 + i) * D_INNER + d0 + tx] = __float2half_rn(v);
    }
    __syncthreads();
#pragma unroll
    for (int i = ty; i < 32; i += 8) {
        size_t o = (size_t)(d0 + i) * NROWS + b * SEQ + l0 + tx;
        xcT[o] = __float2half_rn(tout[tx][i]);
        zT[o]  = __float2half_rn(tz[tx][i]);
    }
}

// ========== fused chunked selective scan, SCH=4 channels per block =========
__global__ void __launch_bounds__(256)
scan_fused_kernel(const fp16* __restrict__ dtT, const fp16* __restrict__ xcT,
                  const fp16* __restrict__ zT,  const float* __restrict__ xdbc,
                  const float* __restrict__ A_log, const float* __restrict__ Dv,
                  fp16* __restrict__ yh)
{
    __shared__ float sP[NCH][SCH][D_STATE];
    __shared__ float sS[NCH][SCH][D_STATE];

    const int blk = blockIdx.x;
    const int dgrp = blk & (D_INNER / SCH - 1);
    const int b    = blk >> 9;
    const int d0   = dgrp * SCH;
    const int t = threadIdx.x;
    const int n = t & 15, c = t >> 4;

    float An[SCH], Dd[SCH];
#pragma unroll
    for (int ch = 0; ch < SCH; ch++) {
        An[ch] = -expf(A_log[(d0 + ch) * D_STATE + n]);
        Dd[ch] = Dv[d0 + ch];
    }

    const size_t base = (size_t)d0 * NROWS + b * SEQ + c * CHT;
    const fp16* dtp = dtT + base;
    const fp16* xcp = xcT + base;
    const fp16* zp  = zT  + base;
    const float* bc0 = xdbc + ((size_t)(b * SEQ + c * CHT)) * XPROJ_N;

    // ---- Phase A ----
    {
        const float* bc = bc0;
        float P[SCH], S[SCH];
#pragma unroll
        for (int ch = 0; ch < SCH; ch++) { P[ch] = 1.f; S[ch] = 0.f; }
        for (int l0 = 0; l0 < CHT; l0 += 4) {
            float dt4[SCH][4], xc4[SCH][4];
#pragma unroll
            for (int ch = 0; ch < SCH; ch++) {
                load4h(dtp + (size_t)ch * NROWS + l0, dt4[ch]);
                load4h(xcp + (size_t)ch * NROWS + l0, xc4[ch]);
            }
#pragma unroll
            for (int j = 0; j < 4; j++) {
                float Bn = bc[DT_RANK + n];
#pragma unroll
                for (int ch = 0; ch < SCH; ch++) {
                    float a = __expf(dt4[ch][j] * An[ch]);
                    S[ch] = fmaf(a, S[ch], dt4[ch][j] * xc4[ch][j] * Bn);
                    P[ch] *= a;
                }
                bc += XPROJ_N;
            }
        }
#pragma unroll
        for (int ch = 0; ch < SCH; ch++) { sP[c][ch][n] = P[ch]; sS[c][ch][n] = S[ch]; }
    }
    __syncthreads();

    // ---- Phase B ----
    float h[SCH];
#pragma unroll
    for (int ch = 0; ch < SCH; ch++) h[ch] = 0.f;
    for (int cc = 0; cc < c; cc++)
#pragma unroll
        for (int ch = 0; ch < SCH; ch++)
            h[ch] = fmaf(sP[cc][ch][n], h[ch], sS[cc][ch][n]);

    // ---- Phase C ----
    const float* bc = bc0;
    size_t yrow = (size_t)(b * SEQ + c * CHT) * D_INNER + d0;

    for (int l0 = 0; l0 < CHT; l0 += 4) {
        float dt4[SCH][4], xc4[SCH][4];
#pragma unroll
        for (int ch = 0; ch < SCH; ch++) {
            load4h(dtp + (size_t)ch * NROWS + l0, dt4[ch]);
            load4h(xcp + (size_t)ch * NROWS + l0, xc4[ch]);
        }
#pragma unroll
        for (int j = 0; j < 4; j++) {
            float Bn = bc[DT_RANK + n];
            float Cn = bc[DT_RANK + D_STATE + n];
            float part[SCH];
#pragma unroll
            for (int ch = 0; ch < SCH; ch++) {
                float a = __expf(dt4[ch][j] * An[ch]);
                h[ch] = fmaf(a, h[ch], dt4[ch][j] * xc4[ch][j] * Bn);
                part[ch] = Cn * h[ch];
            }
#pragma unroll
            for (int ch = 0; ch < SCH; ch++) {
                part[ch] += __shfl_xor_sync(0xffffffffu, part[ch], 1);
                part[ch] += __shfl_xor_sync(0xffffffffu, part[ch], 2);
                part[ch] += __shfl_xor_sync(0xffffffffu, part[ch], 4);
                part[ch] += __shfl_xor_sync(0xffffffffu, part[ch], 8);
            }
            if (n == 0) {
                float z0 = __half2float(zp[l0 + j]);
                float z1 = __half2float(zp[(size_t)1 * NROWS + l0 + j]);
                float z2 = __half2float(zp[(size_t)2 * NROWS + l0 + j]);
                float z3 = __half2float(zp[(size_t)3 * NROWS + l0 + j]);
                float g0 = z0 / (1.f + __expf(-z0));
                float g1 = z1 / (1.f + __expf(-z1));
                float g2 = z2 / (1.f + __expf(-z2));
                float g3 = z3 / (1.f + __expf(-z3));
                __half2 o01 = __floats2half2_rn(
                    (part[0] + xc4[0][j] * Dd[0]) * g0,
                    (part[1] + xc4[1][j] * Dd[1]) * g1);
                __half2 o23 = __floats2half2_rn(
                    (part[2] + xc4[2][j] * Dd[2]) * g2,
                    (part[3] + xc4[3][j] * Dd[3]) * g3);
                uint2 ov;
                ov.x = *reinterpret_cast<uint32_t*>(&o01);
                ov.y = *reinterpret_cast<uint32_t*>(&o23);
                *reinterpret_cast<uint2*>(&yh[yrow]) = ov;
            }
            bc += XPROJ_N;
            yrow += D_INNER;
        }
    }
}

// ---------------- launcher -------------------------------------------------
extern "C" void kernel_launch(void* const* d_in, const int* in_sizes, int n_in,
                              void* d_out, int out_size)
{
    const float* x       = (const float*)d_in[0];
    const float* w_in    = (const float*)d_in[1];
    const float* w_conv  = (const float*)d_in[2];
    const float* b_conv  = (const float*)d_in[3];
    const float* w_xproj = (const float*)d_in[4];
    const float* w_dt    = (const float*)d_in[5];
    const float* b_dt    = (const float*)d_in[6];
    const float* A_log   = (const float*)d_in[7];
    const float* Dv      = (const float*)d_in[8];
    const float* w_out   = (const float*)d_in[9];
    float* out = (float*)d_out;

    float *xz, *xdbc, *part;
    fp16 *dtT, *xcT, *zT;
    fp16 *xh, *xch, *xdh, *yh;
    fp16 *winT, *woutT, *wxT, *wdtT;
    cudaGetSymbolAddress((void**)&xz,    g_xz);
    cudaGetSymbolAddress((void**)&xdbc,  g_xdbc);
    cudaGetSymbolAddress((void**)&part,  g_part);
    cudaGetSymbolAddress((void**)&dtT,   g_dtT);
    cudaGetSymbolAddress((void**)&xcT,   g_xcT);
    cudaGetSymbolAddress((void**)&zT,    g_zT);
    cudaGetSymbolAddress((void**)&xh,    g_xh);
    cudaGetSymbolAddress((void**)&xch,   g_xconvh);
    cudaGetSymbolAddress((void**)&xdh,   g_xdh);
    cudaGetSymbolAddress((void**)&yh,    g_yh);
    cudaGetSymbolAddress((void**)&winT,  g_winT);
    cudaGetSymbolAddress((void**)&woutT, g_woutT);
    cudaGetSymbolAddress((void**)&wxT,   g_wxT);
    cudaGetSymbolAddress((void**)&wdtT,  g_wdtT);

    cudaFuncSetAttribute(gemm1p, cudaFuncAttributeMaxDynamicSharedMemorySize,
                         SMEM_TOT);

    dim3 tb(32, 8);
    // 0: unified prep (input convert + all weight transposes)
    prep_kernel<<<PREP_TOTAL, 256>>>(x, xh, w_in, winT, w_xproj, wxT,
                                     w_dt, wdtT, w_out, woutT);
    // 1: xz = x @ w_in   (fp32 output, as in R14)
    gemm1p<<<dim3(32, 32, 1), 256, SMEM_TOT>>>(xh, winT, xz, nullptr,
                                               2 * D_INNER, D_MODEL, 0,
                                               D_MODEL / 32, 2 * D_INNER,
                                               nullptr, 0, 0);
    // 2: fused conv + silu + transposes (fp32 xz)
    convT_kernel<<<dim3(SEQ / 32, D_INNER / 32, B_SZ), tb>>>(
        xz, w_conv, b_conv, xcT, zT, xch);
    // 3: xproj split-K GEMM
    gemm1p<<<dim3(1, 32, KSPLIT3), 256, SMEM_TOT>>>(
        xch, wxT, part, nullptr,
        XPROJ_NPAD, D_INNER, 0, (D_INNER / 32) / KSPLIT3, XPROJ_NPAD,
        nullptr, 0, (size_t)NROWS * XPROJ_NPAD);
    // 4: reduce partials (+ dt-rank fp16)
    reduce3_kernel<<<(NROWS * XPROJ_N + 255) / 256, 256>>>(part, xdbc, xdh);
    // 5: dtT = softplus(wdtT @ xdh^T + b_dt[d])  (fp16, transposed layout)
    gemm1p<<<dim3(NROWS / 128, D_INNER / 128, 1), 256, SMEM_TOT>>>(
        wdtT, xdh, nullptr, dtT,
        NROWS, DT_RANK, 0, DT_RANK / 32, NROWS,
        b_dt, 2, 0);
    // 6: fused chunked scan
    scan_fused_kernel<<<B_SZ * D_INNER / SCH, 256>>>(
        dtT, xcT, zT, xdbc, A_log, Dv, yh);
    // 7: out = y @ w_out
    gemm1p<<<dim3(8, 32, 1), 256, SMEM_TOT>>>(yh, woutT, out, nullptr,
                                              D_MODEL, D_INNER, 0,
                                              D_INNER / 32, D_MODEL,
                                              nullptr, 0, 0);
}